// round 6
// baseline (speedup 1.0000x reference)
#include <cuda_runtime.h>
#include <cuda_bf16.h>
#include <cstdint>

#define SEQ 1024
#define DH  64
#define NBH 64
#define MT  128
#define NC  128

#define S1  144   // bytes per row, 64-col bf16 tile (128B data + 16 pad)
#define S2  272   // bytes per row, 128-col bf16 tile (256B data + 16 pad)

#define P1_QH 0
#define P1_QL 18432
#define P1_KH 36864
#define P1_KL 55296
#define P2_WH 0
#define P2_WL 34816
#define P2_VH 69632
#define P2_VL 87040
#define ST_SUM 104448              // 128 * 16 floats
#define ST_INV (ST_SUM + 8192)     // 128 floats
#define SMEM_TOTAL (ST_INV + 512 + 256)

__device__ __forceinline__ uint32_t sm_u32(const void* p) {
    uint32_t a;
    asm("{ .reg .u64 t; cvta.to.shared.u64 t, %1; cvt.u32.u64 %0, t; }" : "=r"(a) : "l"(p));
    return a;
}
__device__ __forceinline__ uint32_t pack2(__nv_bfloat16 a, __nv_bfloat16 b) {
    return (uint32_t)__bfloat16_as_ushort(a) | ((uint32_t)__bfloat16_as_ushort(b) << 16);
}
__device__ __forceinline__ void split4(float4 v, uint2& h, uint2& l) {
    __nv_bfloat16 h0 = __float2bfloat16(v.x), h1 = __float2bfloat16(v.y);
    __nv_bfloat16 h2 = __float2bfloat16(v.z), h3 = __float2bfloat16(v.w);
    __nv_bfloat16 l0 = __float2bfloat16(v.x - __bfloat162float(h0));
    __nv_bfloat16 l1 = __float2bfloat16(v.y - __bfloat162float(h1));
    __nv_bfloat16 l2 = __float2bfloat16(v.z - __bfloat162float(h2));
    __nv_bfloat16 l3 = __float2bfloat16(v.w - __bfloat162float(h3));
    h.x = pack2(h0, h1); h.y = pack2(h2, h3);
    l.x = pack2(l0, l1); l.y = pack2(l2, l3);
}

#define LDSM4(a, addr) \
    asm volatile("ldmatrix.sync.aligned.m8n8.x4.shared.b16 {%0,%1,%2,%3}, [%4];" \
        : "=r"((a)[0]), "=r"((a)[1]), "=r"((a)[2]), "=r"((a)[3]) : "r"(addr))

__device__ __forceinline__ void mma_bf16(float* c, const uint32_t* a, uint32_t b0, uint32_t b1) {
    asm volatile("mma.sync.aligned.m16n8k16.row.col.f32.bf16.bf16.f32 "
        "{%0,%1,%2,%3}, {%4,%5,%6,%7}, {%8,%9}, {%0,%1,%2,%3};"
        : "+f"(c[0]), "+f"(c[1]), "+f"(c[2]), "+f"(c[3])
        : "r"(a[0]), "r"(a[1]), "r"(a[2]), "r"(a[3]), "r"(b0), "r"(b1));
}

__global__ __launch_bounds__(512, 1)
void attn_fused(const float* __restrict__ Qg, const float* __restrict__ Kg,
                const float* __restrict__ Vg, const float* __restrict__ bias,
                float* __restrict__ outO, float* __restrict__ outW)
{
    extern __shared__ char sm[];
    const uint32_t sb = sm_u32(sm);
    const int tid = threadIdx.x;
    const int lane = tid & 31, wid = tid >> 5;
    const int gid = lane >> 2, tig = lane & 3;
    const int wm = wid >> 2, wn = wid & 3;       // 4 x 4 warp grid
    const int bh = blockIdx.y, qb = blockIdx.x * MT;

    // ---- convert Q tile (pre-scaled, hi/lo split) ----
    {
        const float* Qp = Qg + ((size_t)bh * SEQ + qb) * DH;
        int r = tid >> 2, c0 = (tid & 3) * 16;
        #pragma unroll
        for (int j = 0; j < 4; ++j) {
            float4 v = *(const float4*)(Qp + r * DH + c0 + j * 4);
            v.x *= 0.125f; v.y *= 0.125f; v.z *= 0.125f; v.w *= 0.125f;
            uint2 h, l; split4(v, h, l);
            *(uint2*)(sm + P1_QH + r * S1 + (c0 + j * 4) * 2) = h;
            *(uint2*)(sm + P1_QL + r * S1 + (c0 + j * 4) * 2) = l;
        }
    }
    __syncthreads();

    // ---- preload Q fragments ----
    uint32_t aqh[4][2][4], aql[4][2][4];
    #pragma unroll
    for (int kt = 0; kt < 4; ++kt)
        #pragma unroll
        for (int mi = 0; mi < 2; ++mi) {
            uint32_t ra = sb + P1_QH + (uint32_t)((wm * 32 + mi * 16 + (lane & 15)) * S1
                         + (lane >> 4) * 16 + kt * 32);
            LDSM4(aqh[kt][mi], ra);
            LDSM4(aql[kt][mi], ra + (P1_QL - P1_QH));
        }

    float rs[2][2] = {{0.f, 0.f}, {0.f, 0.f}};

    // ================= phase 1: E = exp(scores) -> outW, row sums =================
    for (int nc = 0; nc < 8; ++nc) {
        __syncthreads();
        {   // convert K chunk
            const float* Kp = Kg + ((size_t)bh * SEQ + nc * NC) * DH;
            int r = tid >> 2, c0 = (tid & 3) * 16;
            #pragma unroll
            for (int j = 0; j < 4; ++j) {
                float4 v = *(const float4*)(Kp + r * DH + c0 + j * 4);
                uint2 h, l; split4(v, h, l);
                *(uint2*)(sm + P1_KH + r * S1 + (c0 + j * 4) * 2) = h;
                *(uint2*)(sm + P1_KL + r * S1 + (c0 + j * 4) * 2) = l;
            }
        }
        __syncthreads();

        float acc[2][4][4];
        #pragma unroll
        for (int mi = 0; mi < 2; ++mi)
            #pragma unroll
            for (int ni = 0; ni < 4; ++ni)
                #pragma unroll
                for (int e = 0; e < 4; ++e) acc[mi][ni][e] = 0.f;

        #pragma unroll
        for (int kt = 0; kt < 4; ++kt) {
            uint32_t bh4[2][4], bl4[2][4];
            #pragma unroll
            for (int p = 0; p < 2; ++p) {
                uint32_t addr = sb + P1_KH + (uint32_t)((wn * 32 + p * 16 + (lane & 15)) * S1
                               + (lane >> 4) * 16 + kt * 32);
                LDSM4(bh4[p], addr);
                LDSM4(bl4[p], addr + (P1_KL - P1_KH));
            }
            #pragma unroll
            for (int p = 0; p < 2; ++p)
                #pragma unroll
                for (int q = 0; q < 2; ++q) {
                    uint32_t b0h = bh4[p][q], b1h = bh4[p][q + 2];
                    uint32_t b0l = bl4[p][q], b1l = bl4[p][q + 2];
                    #pragma unroll
                    for (int mi = 0; mi < 2; ++mi) {
                        float* c = acc[mi][p * 2 + q];
                        mma_bf16(c, aqh[kt][mi], b0h, b1h);
                        mma_bf16(c, aqh[kt][mi], b0l, b1l);
                        mma_bf16(c, aql[kt][mi], b0h, b1h);
                    }
                }
        }
        // epilogue: +bias, exp, store E, accumulate sums
        #pragma unroll
        for (int mi = 0; mi < 2; ++mi) {
            int r0 = qb + wm * 32 + mi * 16 + gid;
            #pragma unroll
            for (int ni = 0; ni < 4; ++ni) {
                int c = nc * NC + wn * 32 + ni * 8 + tig * 2;
                float2 b0 = *(const float2*)(bias + (size_t)r0 * SEQ + c);
                float e0 = __expf(acc[mi][ni][0] + b0.x);
                float e1 = __expf(acc[mi][ni][1] + b0.y);
                *(float2*)(outW + ((size_t)bh * SEQ + r0) * SEQ + c) = make_float2(e0, e1);
                rs[mi][0] += e0 + e1;
                float2 b1 = *(const float2*)(bias + (size_t)(r0 + 8) * SEQ + c);
                float e2 = __expf(acc[mi][ni][2] + b1.x);
                float e3 = __expf(acc[mi][ni][3] + b1.y);
                *(float2*)(outW + ((size_t)bh * SEQ + r0 + 8) * SEQ + c) = make_float2(e2, e3);
                rs[mi][1] += e2 + e3;
            }
        }
    }

    // ---- reduce per-row sums -> 1/sum ----
    {
        float* st = (float*)(sm + ST_SUM);
        int slot = wn * 4 + tig;
        #pragma unroll
        for (int mi = 0; mi < 2; ++mi)
            #pragma unroll
            for (int h = 0; h < 2; ++h) {
                int r = wm * 32 + mi * 16 + h * 8 + gid;
                st[r * 16 + slot] = rs[mi][h];
            }
    }
    __syncthreads();
    if (tid < 128) {
        float* st = (float*)(sm + ST_SUM);
        float s = 0.f;
        #pragma unroll
        for (int i = 0; i < 16; ++i) s += st[tid * 16 + i];
        ((float*)(sm + ST_INV))[tid] = 1.f / s;
    }

    // ================= phase 2: W = E * inv, O = W @ V =================
    float accO[2][2][4];
    #pragma unroll
    for (int mi = 0; mi < 2; ++mi)
        #pragma unroll
        for (int ni = 0; ni < 2; ++ni)
            #pragma unroll
            for (int e = 0; e < 4; ++e) accO[mi][ni][e] = 0.f;

    const float* sInv = (const float*)(sm + ST_INV);

    for (int nc = 0; nc < 8; ++nc) {
        __syncthreads();
        {   // normalize E -> W (in place), split to smem
            int r = tid >> 2, c0 = (tid & 3) * 32;
            float inv = sInv[r];
            float* Wp = outW + ((size_t)bh * SEQ + qb + r) * SEQ + nc * NC + c0;
            #pragma unroll
            for (int j = 0; j < 8; ++j) {
                float4 e = *(float4*)(Wp + j * 4);
                float4 w = make_float4(e.x * inv, e.y * inv, e.z * inv, e.w * inv);
                *(float4*)(Wp + j * 4) = w;
                uint2 h, l; split4(w, h, l);
                *(uint2*)(sm + P2_WH + r * S2 + (c0 + j * 4) * 2) = h;
                *(uint2*)(sm + P2_WL + r * S2 + (c0 + j * 4) * 2) = l;
            }
        }
        {   // V chunk -> transposed split smem [d][s]
            int s0 = (tid & 63) * 2, d0 = (tid >> 6) * 8;
            const float* vp = Vg + ((size_t)bh * SEQ + nc * NC + s0) * DH + d0;
            float va[8], vb[8];
            *(float4*)(va)     = *(const float4*)(vp);
            *(float4*)(va + 4) = *(const float4*)(vp + 4);
            *(float4*)(vb)     = *(const float4*)(vp + DH);
            *(float4*)(vb + 4) = *(const float4*)(vp + DH + 4);
            #pragma unroll
            for (int d = 0; d < 8; ++d) {
                __nv_bfloat16 ha = __float2bfloat16(va[d]);
                __nv_bfloat16 hb = __float2bfloat16(vb[d]);
                __nv_bfloat16 la = __float2bfloat16(va[d] - __bfloat162float(ha));
                __nv_bfloat16 lb = __float2bfloat16(vb[d] - __bfloat162float(hb));
                *(uint32_t*)(sm + P2_VH + (d0 + d) * S2 + s0 * 2) = pack2(ha, hb);
                *(uint32_t*)(sm + P2_VL + (d0 + d) * S2 + s0 * 2) = pack2(la, lb);
            }
        }
        __syncthreads();

        #pragma unroll
        for (int kt = 0; kt < 8; ++kt) {
            uint32_t awh[2][4], awl[2][4];
            #pragma unroll
            for (int mi = 0; mi < 2; ++mi) {
                uint32_t ra = sb + P2_WH + (uint32_t)((wm * 32 + mi * 16 + (lane & 15)) * S2
                             + (lane >> 4) * 16 + kt * 32);
                LDSM4(awh[mi], ra);
                LDSM4(awl[mi], ra + (P2_WL - P2_WH));
            }
            uint32_t bvh[4], bvl[4];
            {
                uint32_t addr = sb + P2_VH + (uint32_t)((wn * 16 + (lane & 15)) * S2
                               + (lane >> 4) * 16 + kt * 32);
                LDSM4(bvh, addr);
                LDSM4(bvl, addr + (P2_VL - P2_VH));
            }
            #pragma unroll
            for (int q = 0; q < 2; ++q) {
                uint32_t b0h = bvh[q], b1h = bvh[q + 2];
                uint32_t b0l = bvl[q], b1l = bvl[q + 2];
                #pragma unroll
                for (int mi = 0; mi < 2; ++mi) {
                    float* c = accO[mi][q];
                    mma_bf16(c, awh[mi], b0h, b1h);
                    mma_bf16(c, awh[mi], b0l, b1l);
                    mma_bf16(c, awl[mi], b0h, b1h);
                }
            }
        }
    }

    // ---- O epilogue ----
    #pragma unroll
    for (int mi = 0; mi < 2; ++mi) {
        int r0 = qb + wm * 32 + mi * 16 + gid;
        #pragma unroll
        for (int ni = 0; ni < 2; ++ni) {
            int c = wn * 16 + ni * 8 + tig * 2;
            *(float2*)(outO + ((size_t)bh * SEQ + r0) * DH + c) =
                make_float2(accO[mi][ni][0], accO[mi][ni][1]);
            *(float2*)(outO + ((size_t)bh * SEQ + r0 + 8) * DH + c) =
                make_float2(accO[mi][ni][2], accO[mi][ni][3]);
        }
    }
}

extern "C" void kernel_launch(void* const* d_in, const int* in_sizes, int n_in,
                              void* d_out, int out_size) {
    const float* Q    = (const float*)d_in[0];
    const float* K    = (const float*)d_in[1];
    const float* V    = (const float*)d_in[2];
    const float* bias = (const float*)d_in[3];
    float* outO = (float*)d_out;
    float* outW = outO + (size_t)NBH * SEQ * DH;

    static int inited = 0;
    if (!inited) {
        cudaFuncSetAttribute(attn_fused, cudaFuncAttributeMaxDynamicSharedMemorySize, SMEM_TOTAL);
        inited = 1;
    }
    dim3 grid(SEQ / MT, NBH);
    attn_fused<<<grid, 512, SMEM_TOTAL>>>(Q, K, V, bias, outO, outW);
}